// round 16
// baseline (speedup 1.0000x reference)
#include <cuda_runtime.h>
#include <cuda_fp16.h>
#include <cuda_bf16.h>
#include <cstdint>

// ============================================================================
// VQ quantizer: single-pass fp16 mma.sync prefilter (per-row rigorous error
// bound) + provably-exact fp32 argmin rescue.
// R15: 3 CTAs/SM (6 warps/SMSP). A fragments built from GMEM (no A smem, no
// staging phase); B at 128B stride with odd-row half-swap => conflict-free
// LDS.128; packed-key IMNMX top-3 scan (R14); fused loss finalize.
// z [N,64] f32, codebook [512,64] f32.
// Outputs (concatenated f32): q_ste [N*64], loss [1], ids [N] (as float).
// ============================================================================

#define D        64
#define KCODES   512
#define MTILE    128
#define TPB      256
#define GRID_MAX 444   // 3 CTAs/SM x 148 SMs

// smem layout (byte offsets)
#define B_OFF      0        // 512 x 128B fp16 codebook rows (permuted+halfswap)
#define C2N_OFF    65536    // 512 f32: -0.5*||c||^2
#define KID_OFF    67584    // 128 int
#define CN_OFF     68096    // 1 f32: max ||c||
#define SMEM_TOTAL 68112

#define KEYMASK 0xFFFFFE00u   // top 23 bits = biased score, low 9 = 511-k

__device__ double       g_partial[4096];
__device__ unsigned int g_count = 0;

// ---------------- helpers ----------------
__device__ __forceinline__ void mma_fp16(float* c, const uint32_t* a,
                                         uint32_t b0, uint32_t b1) {
    asm volatile(
        "mma.sync.aligned.m16n8k16.row.col.f32.f16.f16.f32 "
        "{%0,%1,%2,%3}, {%4,%5,%6,%7}, {%8,%9}, {%0,%1,%2,%3};"
        : "+f"(c[0]), "+f"(c[1]), "+f"(c[2]), "+f"(c[3])
        : "r"(a[0]), "r"(a[1]), "r"(a[2]), "r"(a[3]), "r"(b0), "r"(b1));
}

// packed key: bits(v + 4.0) masked, low 9 bits = 511-k (ties -> smaller k)
__device__ __forceinline__ uint32_t mkkey(float v, uint32_t idx) {
    return (__float_as_uint(v + 4.0f) & KEYMASK) | idx;
}

// branchless top-3 insert over packed keys (descending), 5 IMNMX
__device__ __forceinline__ void ins3k(uint32_t x, uint32_t* t) {
    uint32_t a = min(x, t[0]); t[0] = max(x, t[0]);
    uint32_t b = min(a, t[1]); t[1] = max(a, t[1]);
    t[2] = max(b, t[2]);
}

// EXACT scorer — replicates round-1 arithmetic (verified rel_err 0.0)
__device__ __forceinline__ float exact_d2(const float4* zr, float z2,
                                          const float* __restrict__ crow) {
    const float4* c4 = (const float4*)crow;
    float4 cv[16];
    #pragma unroll
    for (int i = 0; i < 16; i++) cv[i] = c4[i];
    float c2 = 0.f;
    #pragma unroll
    for (int i = 0; i < 16; i++) {
        c2 += cv[i].x * cv[i].x; c2 += cv[i].y * cv[i].y;
        c2 += cv[i].z * cv[i].z; c2 += cv[i].w * cv[i].w;
    }
    float a0 = 0.f, a1 = 0.f, a2 = 0.f, a3 = 0.f;
    #pragma unroll
    for (int i = 0; i < 16; i++) {
        a0 += zr[i].x * cv[i].x;
        a1 += zr[i].y * cv[i].y;
        a2 += zr[i].z * cv[i].z;
        a3 += zr[i].w * cv[i].w;
    }
    float dot = (a0 + a1) + (a2 + a3);
    return (z2 - 2.0f * dot) + c2;
}

__device__ __forceinline__ float z2_of(const float4* zr) {
    float z2 = 0.f;
    #pragma unroll
    for (int i = 0; i < 16; i++)
        z2 += zr[i].x * zr[i].x + zr[i].y * zr[i].y
            + zr[i].z * zr[i].z + zr[i].w * zr[i].w;
    return z2;
}

__device__ __forceinline__ uint32_t packh2(float x, float y) {
    __nv_half2_raw h2 = __halves2half2(__float2half_rn(x), __float2half_rn(y));
    return *(uint32_t*)&h2;
}

// B row: convert + store PERMUTED at 128B stride. Thread (qr,qc) reads its
// 8 fragment words at byte offset qc*32: k0..31 half at +((row&1)*16),
// k32..63 half at +(16-(row&1)*16)  (odd-row half-swap => conflict-free).
__device__ __forceinline__ float stage_row_b_perm(char* dst, const float4* v,
                                                  int odd) {
    float s = 0.f;
    uint32_t w[32];
    #pragma unroll
    for (int i = 0; i < 16; i++) {
        float4 a = v[i];
        s += a.x * a.x + a.y * a.y + a.z * a.z + a.w * a.w;
        w[2 * i]     = packh2(a.x, a.y);
        w[2 * i + 1] = packh2(a.z, a.w);
    }
    const int oA = odd * 16;
    const int oB = 16 - oA;
    *(uint4*)(dst +  0 + oA) = make_uint4(w[0],  w[4],  w[8],  w[12]);
    *(uint4*)(dst +  0 + oB) = make_uint4(w[16], w[20], w[24], w[28]);
    *(uint4*)(dst + 32 + oA) = make_uint4(w[1],  w[5],  w[9],  w[13]);
    *(uint4*)(dst + 32 + oB) = make_uint4(w[17], w[21], w[25], w[29]);
    *(uint4*)(dst + 64 + oA) = make_uint4(w[2],  w[6],  w[10], w[14]);
    *(uint4*)(dst + 64 + oB) = make_uint4(w[18], w[22], w[26], w[30]);
    *(uint4*)(dst + 96 + oA) = make_uint4(w[3],  w[7],  w[11], w[15]);
    *(uint4*)(dst + 96 + oB) = make_uint4(w[19], w[23], w[27], w[31]);
    return s;
}

// ============================================================================
// Main kernel: persistent, 3 CTAs/SM, 8 warps, M-tile 128 (1 m16 strip/warp)
// ============================================================================
__global__ __launch_bounds__(TPB, 3)
void vq_mma(const float* __restrict__ z, const float* __restrict__ cb,
            int N, float* __restrict__ q_out, float* __restrict__ ids_out,
            float* __restrict__ loss_out)
{
    extern __shared__ char smem[];
    const int tid  = threadIdx.x;
    const int wid  = tid >> 5;
    const int lane = tid & 31;
    const int qr   = lane >> 2;   // 0..7
    const int qc   = lane & 3;    // 0..3
    const int sA   = (qr & 1) * 16;   // odd-row half-swap load offsets
    const int sB   = 16 - sA;

    float* c2n  = (float*)(smem + C2N_OFF);
    int*   kidS = (int*)(smem + KID_OFF);
    float* cnp  = (float*)(smem + CN_OFF);

    // ---- stage codebook once: permuted fp16 rows + -0.5*||c||^2 ----
    for (int n = tid; n < KCODES; n += TPB) {
        float4 cv[16];
        const float4* c4 = (const float4*)(cb + (size_t)n * D);
        #pragma unroll
        for (int i = 0; i < 16; i++) cv[i] = c4[i];
        float s = stage_row_b_perm(smem + B_OFF + n * 128, cv, n & 1);
        c2n[n] = -0.5f * s;
    }
    __syncthreads();
    if (tid < 32) {
        float m = 0.f;
        for (int i = tid; i < KCODES; i += 32) m = fmaxf(m, -c2n[i]);
        #pragma unroll
        for (int off = 16; off; off >>= 1)
            m = fmaxf(m, __shfl_xor_sync(0xffffffffu, m, off));
        if (tid == 0) *cnp = sqrtf(2.0f * m);
    }
    __syncthreads();
    const float CNMAX = *cnp;

    const int ntiles = N / MTILE;
    double dsum = 0.0;

    for (int tile = blockIdx.x; tile < ntiles; tile += gridDim.x) {
        // ---- A fragments straight from GMEM (rows wid*16+qr, +8) ----
        uint32_t afr[4][4];
        float z2r0, z2r1;
        {
            const float* zr0 = z + (size_t)(tile * MTILE + wid * 16 + qr) * D;
            const float* zr1 = zr0 + 8 * D;
            float s0 = 0.f, s1 = 0.f;
            #pragma unroll
            for (int ks = 0; ks < 4; ks++) {
                float2 a0 = *(const float2*)(zr0 + ks * 16 + qc * 2);
                float2 b0 = *(const float2*)(zr0 + ks * 16 + 8 + qc * 2);
                float2 a1 = *(const float2*)(zr1 + ks * 16 + qc * 2);
                float2 b1 = *(const float2*)(zr1 + ks * 16 + 8 + qc * 2);
                s0 += a0.x * a0.x + a0.y * a0.y + b0.x * b0.x + b0.y * b0.y;
                s1 += a1.x * a1.x + a1.y * a1.y + b1.x * b1.x + b1.y * b1.y;
                afr[ks][0] = packh2(a0.x, a0.y);
                afr[ks][1] = packh2(a1.x, a1.y);
                afr[ks][2] = packh2(b0.x, b0.y);
                afr[ks][3] = packh2(b1.x, b1.y);
            }
            // quad reduce: all 4 qc lanes of a row get the full approx ||z||^2
            s0 += __shfl_xor_sync(0xffffffffu, s0, 1);
            s0 += __shfl_xor_sync(0xffffffffu, s0, 2);
            s1 += __shfl_xor_sync(0xffffffffu, s1, 1);
            s1 += __shfl_xor_sync(0xffffffffu, s1, 2);
            z2r0 = s0; z2r1 = s1;
        }

        // ---- MMA + per-thread packed-key top-3 for 2 row-slots ----
        uint32_t tkey[2][3];
        #pragma unroll
        for (int s = 0; s < 2; s++)
            tkey[s][0] = tkey[s][1] = tkey[s][2] = 0u;

        for (int grp = 0; grp < 32; grp++) {   // 32 groups of 16 codes
            float acc[2][4];
            uint4 ra[2], rb[2];
            #pragma unroll
            for (int c = 0; c < 2; c++) {
                const int col0 = grp * 16 + c * 8 + qc * 2;
                const float2 nh = *(const float2*)&c2n[col0];
                acc[c][0] = nh.x; acc[c][1] = nh.y;   // init = -0.5*||c||^2
                acc[c][2] = nh.x; acc[c][3] = nh.y;
                const char* bp = smem + B_OFF
                               + (grp * 16 + c * 8 + qr) * 128 + qc * 32;
                ra[c] = *(const uint4*)(bp + sA);
                rb[c] = *(const uint4*)(bp + sB);
            }
            #pragma unroll
            for (int c = 0; c < 2; c++) mma_fp16(acc[c], afr[0], ra[c].x, ra[c].y);
            #pragma unroll
            for (int c = 0; c < 2; c++) mma_fp16(acc[c], afr[1], ra[c].z, ra[c].w);
            #pragma unroll
            for (int c = 0; c < 2; c++) mma_fp16(acc[c], afr[2], rb[c].x, rb[c].y);
            #pragma unroll
            for (int c = 0; c < 2; c++) mma_fp16(acc[c], afr[3], rb[c].z, rb[c].w);

            #pragma unroll
            for (int c = 0; c < 2; c++) {
                const int col0 = grp * 16 + c * 8 + qc * 2;
                const uint32_t i0 = 511 - col0;
                ins3k(mkkey(acc[c][0], i0),     tkey[0]);
                ins3k(mkkey(acc[c][1], i0 - 1), tkey[0]);
                ins3k(mkkey(acc[c][2], i0),     tkey[1]);
                ins3k(mkkey(acc[c][3], i0 - 1), tkey[1]);
            }
        }

        const uint32_t loc3_0 = tkey[0][2];
        const uint32_t loc3_1 = tkey[1][2];

        // ---- quad merge (xor 1, 2) -> global top-3 per slot ----
        #pragma unroll
        for (int off = 1; off <= 2; off <<= 1) {
            #pragma unroll
            for (int s = 0; s < 2; s++) {
                uint32_t k0 = tkey[s][0], k1 = tkey[s][1], k2 = tkey[s][2];
                uint32_t o0 = __shfl_xor_sync(0xffffffffu, k0, off);
                uint32_t o1 = __shfl_xor_sync(0xffffffffu, k1, off);
                uint32_t o2 = __shfl_xor_sync(0xffffffffu, k2, off);
                ins3k(o0, tkey[s]);
                ins3k(o1, tkey[s]);
                ins3k(o2, tkey[s]);
            }
        }

        // ---- per-row rigorous threshold (fp16 2^-9 bound + key-quant slack) ----
        const float thr0 = sqrtf(z2r0) * CNMAX * 0.001953125f + 1.2e-3f;
        const float thr1 = sqrtf(z2r1) * CNMAX * 0.001953125f + 1.2e-3f;

        const float b1b0 = __uint_as_float(tkey[0][0] & KEYMASK);
        const float b1b1 = __uint_as_float(tkey[1][0] & KEYMASK);
        const uint32_t cut0 = __float_as_uint(b1b0 - thr0) & KEYMASK;
        const uint32_t cut1 = __float_as_uint(b1b1 - thr1) & KEYMASK;

        unsigned bal0 = __ballot_sync(0xffffffffu, loc3_0 >= cut0);
        unsigned bal1 = __ballot_sync(0xffffffffu, loc3_1 >= cut1);
        const unsigned qsh = lane & ~3;
        const bool u0 = ((bal0 >> qsh) & 0xFu) != 0;
        const bool u1 = ((bal1 >> qsh) & 0xFu) != 0;

        // ---- finalize: lane qc=0 -> slot 0, qc=1 -> slot 1 ----
        const bool mine = (qc < 2);
        const int  myrow = wid * 16 + qr + qc * 8;      // valid when mine
        const bool my_unsafe = mine && (qc == 0 ? u0 : u1);
        int kid = 0;

        if (mine && !my_unsafe) {
            const int s = qc;
            const uint32_t K0 = tkey[s][0], K1 = tkey[s][1], K2 = tkey[s][2];
            const uint32_t cut = (s == 0) ? cut0 : cut1;
            int ck[3]; int nc = 1;
            ck[0] = 511 - (int)(K0 & 0x1FFu);
            if (K1 >= cut) ck[nc++] = 511 - (int)(K1 & 0x1FFu);
            if (K2 >= cut) ck[nc++] = 511 - (int)(K2 & 0x1FFu);
            if (nc == 1) {
                kid = ck[0];                            // margin proves winner
            } else {
                if (ck[0] > ck[1]) { int t = ck[0]; ck[0] = ck[1]; ck[1] = t; }
                if (nc == 3) {
                    if (ck[1] > ck[2]) { int t = ck[1]; ck[1] = ck[2]; ck[2] = t; }
                    if (ck[0] > ck[1]) { int t = ck[0]; ck[0] = ck[1]; ck[1] = t; }
                }
                const int grow = tile * MTILE + myrow;
                float4 zr[16];
                const float4* zp = (const float4*)(z + (size_t)grow * D);
                #pragma unroll
                for (int i = 0; i < 16; i++) zr[i] = zp[i];
                const float z2 = z2_of(zr);
                float best = 3.402823466e38f; kid = ck[0];
                for (int i = 0; i < nc; i++) {          // ascending k, strict <
                    float d = exact_d2(zr, z2, cb + (size_t)ck[i] * D);
                    if (d < best) { best = d; kid = ck[i]; }
                }
            }
        }

        // ---- warp-cooperative exact scan for unsafe rows (rare) ----
        unsigned need = __ballot_sync(0xffffffffu, my_unsafe);
        while (need) {
            const int src = __ffs(need) - 1;
            need &= need - 1;
            const int rl = __shfl_sync(0xffffffffu, myrow, src);
            const int grow = tile * MTILE + rl;
            float4 zr[16];
            const float4* zp = (const float4*)(z + (size_t)grow * D);
            #pragma unroll
            for (int i = 0; i < 16; i++) zr[i] = zp[i];
            const float z2 = z2_of(zr);
            float best = 3.402823466e38f; int bk = KCODES;
            for (int k = lane; k < KCODES; k += 32) {   // lane-ascending, strict <
                float d = exact_d2(zr, z2, cb + (size_t)k * D);
                if (d < best) { best = d; bk = k; }
            }
            #pragma unroll
            for (int off = 16; off; off >>= 1) {
                float ob = __shfl_xor_sync(0xffffffffu, best, off);
                int   obk = __shfl_xor_sync(0xffffffffu, bk, off);
                if (ob < best || (ob == best && obk < bk)) { best = ob; bk = obk; }
            }
            if (lane == src) kid = bk;
        }

        if (mine) kidS[myrow] = kid;
        __syncthreads();

        // ---- epilogue: threads 0..127, row tid ----
        if (tid < MTILE) {
            const int grow = tile * MTILE + tid;
            const int k = kidS[tid];
            float4 zr[16];
            const float4* zp = (const float4*)(z + (size_t)grow * D);
            #pragma unroll
            for (int i = 0; i < 16; i++) zr[i] = zp[i];
            const float4* q4 = (const float4*)(cb + (size_t)k * D);
            float4* qo = (float4*)(q_out + (size_t)grow * D);
            float lsum = 0.f;
            #pragma unroll
            for (int i = 0; i < 16; i++) {
                float4 cv = q4[i];
                float4 zv = zr[i];
                float dx = zv.x - cv.x, dy = zv.y - cv.y;
                float dz = zv.z - cv.z, dw = zv.w - cv.w;
                lsum += dx * dx + dy * dy + dz * dz + dw * dw;
                float4 o;
                o.x = zv.x + (cv.x - zv.x);   // fl(z + fl(q - z)), reference STE
                o.y = zv.y + (cv.y - zv.y);
                o.z = zv.z + (cv.z - zv.z);
                o.w = zv.w + (cv.w - zv.w);
                qo[i] = o;
            }
            if (ids_out) ids_out[grow] = (float)k;
            dsum += (double)lsum;
        }
        __syncthreads();   // protect kidS before next iteration's write
    }

    // ---- deterministic per-CTA loss reduction ----
    double* red = (double*)(smem + B_OFF);   // codebook region reusable now
    red[tid] = dsum;
    __syncthreads();
    if (tid == 0) {
        double s = 0.0;
        for (int i = 0; i < TPB; i++) s += red[i];
        g_partial[blockIdx.x] = s;
    }

    // ---- fused finalize: last CTA computes the loss (deterministic order) ----
    if (loss_out) {
        __shared__ unsigned s_last;
        if (tid == 0) {
            __threadfence();
            unsigned p = atomicAdd(&g_count, 1u);
            s_last = (p == gridDim.x - 1) ? 1u : 0u;
        }
        __syncthreads();
        if (s_last) {
            __threadfence();
            double s = 0.0;
            for (int i = tid; i < (int)gridDim.x; i += TPB) s += g_partial[i];
            double* sp = (double*)(smem + B_OFF);
            __syncthreads();
            sp[tid] = s;
            __syncthreads();
            for (int off = TPB / 2; off; off >>= 1) {
                if (tid < off) sp[tid] += sp[tid + off];
                __syncthreads();
            }
            if (tid == 0) {
                double mean = sp[0] / ((double)N * (double)D);
                loss_out[0] = (float)(mean + 0.25 * mean);
                g_count = 0;                 // reset for graph replay
            }
        }
    }
}

// ============================================================================
// Generic fallback (round-2 kernel) for unexpected shapes
// ============================================================================
#define FTPB 256
#define ROW_PAD 68
__global__ __launch_bounds__(FTPB) void vq_ref(
    const float* __restrict__ z, const float* __restrict__ cb,
    int N, int K, float* __restrict__ q_out, float* __restrict__ ids_out)
{
    extern __shared__ float fsm[];
    float* cbs = fsm;
    float* c2  = fsm + (size_t)K * ROW_PAD;
    const int tid = threadIdx.x;
    const float4* cb4 = (const float4*)cb;
    const int nvec = K * (D / 4);
    for (int idx = tid; idx < nvec; idx += FTPB) {
        int k = idx >> 4, c = idx & 15;
        *(float4*)&cbs[k * ROW_PAD + c * 4] = cb4[idx];
    }
    __syncthreads();
    for (int k = tid; k < K; k += FTPB) {
        const float* r = &cbs[k * ROW_PAD];
        float s = 0.f;
        #pragma unroll
        for (int i = 0; i < D; i++) s += r[i] * r[i];
        c2[k] = s;
    }
    __syncthreads();
    const int row = blockIdx.x * FTPB + tid;
    float lsum = 0.f;
    if (row < N) {
        float4 zr[16];
        const float4* zp = (const float4*)(z + (size_t)row * D);
        #pragma unroll
        for (int i = 0; i < 16; i++) zr[i] = zp[i];
        float z2 = 0.f;
        #pragma unroll
        for (int i = 0; i < 16; i++)
            z2 += zr[i].x * zr[i].x + zr[i].y * zr[i].y
                + zr[i].z * zr[i].z + zr[i].w * zr[i].w;
        float best = 3.402823466e38f; int bid = 0;
        for (int k = 0; k < K; k++) {
            const float4* crow = (const float4*)&cbs[k * ROW_PAD];
            float a0 = 0.f, a1 = 0.f, a2 = 0.f, a3 = 0.f;
            #pragma unroll
            for (int i = 0; i < 16; i++) {
                float4 cv = crow[i];
                a0 += zr[i].x * cv.x; a1 += zr[i].y * cv.y;
                a2 += zr[i].z * cv.z; a3 += zr[i].w * cv.w;
            }
            float dot = (a0 + a1) + (a2 + a3);
            float d = (z2 - 2.0f * dot) + c2[k];
            if (d < best) { best = d; bid = k; }
        }
        const float4* crow = (const float4*)&cbs[bid * ROW_PAD];
        float4* qo = (float4*)(q_out + (size_t)row * D);
        #pragma unroll
        for (int i = 0; i < 16; i++) {
            float4 cv = crow[i];
            float4 zv = zr[i];
            float dx = zv.x - cv.x, dy = zv.y - cv.y;
            float dz = zv.z - cv.z, dw = zv.w - cv.w;
            lsum += dx * dx + dy * dy + dz * dz + dw * dw;
            float4 o;
            o.x = zv.x + (cv.x - zv.x); o.y = zv.y + (cv.y - zv.y);
            o.z = zv.z + (cv.z - zv.z); o.w = zv.w + (cv.w - zv.w);
            qo[i] = o;
        }
        if (ids_out) ids_out[row] = (float)bid;
    }
    #pragma unroll
    for (int off = 16; off; off >>= 1)
        lsum += __shfl_down_sync(0xffffffffu, lsum, off);
    __shared__ double wp[FTPB / 32];
    if ((tid & 31) == 0) wp[tid >> 5] = (double)lsum;
    __syncthreads();
    if (tid == 0) {
        double s = 0.0;
        #pragma unroll
        for (int w = 0; w < FTPB / 32; w++) s += wp[w];
        g_partial[blockIdx.x] = s;
    }
}

__global__ void vq_finalize(int nblocks, double inv_total, float* loss_out)
{
    __shared__ double sp[256];
    const int tid = threadIdx.x;
    double s = 0.0;
    for (int i = tid; i < nblocks; i += 256) s += g_partial[i];
    sp[tid] = s;
    __syncthreads();
    for (int off = 128; off; off >>= 1) {
        if (tid < off) sp[tid] += sp[tid + off];
        __syncthreads();
    }
    if (tid == 0) {
        double mean = sp[0] * inv_total;
        loss_out[0] = (float)(mean + 0.25 * mean);
    }
}

extern "C" void kernel_launch(void* const* d_in, const int* in_sizes, int n_in,
                              void* d_out, int out_size)
{
    const float* z  = (const float*)d_in[0];
    const float* cb = (const float*)d_in[1];
    const int N = in_sizes[0] / D;
    const int K = in_sizes[1] / D;

    float* out = (float*)d_out;
    float* q_out    = out;
    float* loss_ptr = nullptr;
    float* ids_ptr  = nullptr;
    const long base = (long)N * D;
    if ((long)out_size >= base + 1 + N) { loss_ptr = out + base; ids_ptr = out + base + 1; }
    else if ((long)out_size == base + N) { ids_ptr = out + base; }
    else if ((long)out_size == base + 1) { loss_ptr = out + base; }

    if (K == KCODES && (N % MTILE) == 0 && N > 0) {
        const int ntiles = N / MTILE;
        const int nblocks = ntiles < GRID_MAX ? ntiles : GRID_MAX;
        cudaFuncSetAttribute(vq_mma, cudaFuncAttributeMaxDynamicSharedMemorySize, SMEM_TOTAL);
        vq_mma<<<nblocks, TPB, SMEM_TOTAL>>>(z, cb, N, q_out, ids_ptr, loss_ptr);
    } else {
        const size_t smem_bytes = ((size_t)K * ROW_PAD + K) * sizeof(float);
        cudaFuncSetAttribute(vq_ref, cudaFuncAttributeMaxDynamicSharedMemorySize, (int)smem_bytes);
        const int nblocks = (N + FTPB - 1) / FTPB;
        vq_ref<<<nblocks, FTPB, smem_bytes>>>(z, cb, N, K, q_out, ids_ptr);
        if (loss_ptr) {
            double inv_total = 1.0 / ((double)N * (double)D);
            vq_finalize<<<1, 256>>>(nblocks, inv_total, loss_ptr);
        }
    }
}

// round 17
// speedup vs baseline: 1.1019x; 1.1019x over previous
#include <cuda_runtime.h>
#include <cuda_fp16.h>
#include <cuda_bf16.h>
#include <cstdint>

// ============================================================================
// VQ quantizer: single-pass fp16 mma.sync prefilter (per-row rigorous error
// bound) + provably-exact fp32 argmin rescue.
// R16 = R14 structure with M=32 rows/warp (M-tile 256): every B fragment is
// reused for 2 m16 strips -> per-row smem traffic halved; 4 indep MMA chains
// kept; packed-key IMNMX top-3 scan; fused loss finalize.
// z [N,64] f32, codebook [512,64] f32.
// Outputs (concatenated f32): q_ste [N*64], loss [1], ids [N] (as float).
// ============================================================================

#define D        64
#define KCODES   512
#define MTILE    256
#define TPB      256
#define GRID_MAX 296   // 2 CTAs/SM x 148 SMs

// smem layout (byte offsets); rows strided 144B => conflict-free LDS.128 frags
#define B_OFF      0        // 512 x 144B fp16 codebook rows (PERMUTED words)
#define A_OFF      73728    // 256 x 144B fp16 z tile (row-major words)
#define C2N_OFF    110592   // 512 f32: -0.5*||c||^2
#define Z2S_OFF    112640   // 256 f32: approx ||z||^2 per tile row
#define KID_OFF    113664   // 256 int
#define CN_OFF     114688   // 1 f32: max ||c||
#define SMEM_TOTAL 114704

#define KEYMASK 0xFFFFFE00u   // top 23 bits = biased score, low 9 = 511-k

__device__ double       g_partial[4096];
__device__ unsigned int g_count = 0;

// ---------------- helpers ----------------
__device__ __forceinline__ void mma_fp16(float* c, const uint32_t* a,
                                         uint32_t b0, uint32_t b1) {
    asm volatile(
        "mma.sync.aligned.m16n8k16.row.col.f32.f16.f16.f32 "
        "{%0,%1,%2,%3}, {%4,%5,%6,%7}, {%8,%9}, {%0,%1,%2,%3};"
        : "+f"(c[0]), "+f"(c[1]), "+f"(c[2]), "+f"(c[3])
        : "r"(a[0]), "r"(a[1]), "r"(a[2]), "r"(a[3]), "r"(b0), "r"(b1));
}

// packed key: bits(v + 4.0) masked, low 9 bits = 511-k (ties -> smaller k)
__device__ __forceinline__ uint32_t mkkey(float v, uint32_t idx) {
    return (__float_as_uint(v + 4.0f) & KEYMASK) | idx;
}

// branchless top-3 insert over packed keys (descending), 5 IMNMX
__device__ __forceinline__ void ins3k(uint32_t x, uint32_t* t) {
    uint32_t a = min(x, t[0]); t[0] = max(x, t[0]);
    uint32_t b = min(a, t[1]); t[1] = max(a, t[1]);
    t[2] = max(b, t[2]);
}

// EXACT scorer — replicates round-1 arithmetic (verified rel_err 0.0)
__device__ __forceinline__ float exact_d2(const float4* zr, float z2,
                                          const float* __restrict__ crow) {
    const float4* c4 = (const float4*)crow;
    float4 cv[16];
    #pragma unroll
    for (int i = 0; i < 16; i++) cv[i] = c4[i];
    float c2 = 0.f;
    #pragma unroll
    for (int i = 0; i < 16; i++) {
        c2 += cv[i].x * cv[i].x; c2 += cv[i].y * cv[i].y;
        c2 += cv[i].z * cv[i].z; c2 += cv[i].w * cv[i].w;
    }
    float a0 = 0.f, a1 = 0.f, a2 = 0.f, a3 = 0.f;
    #pragma unroll
    for (int i = 0; i < 16; i++) {
        a0 += zr[i].x * cv[i].x;
        a1 += zr[i].y * cv[i].y;
        a2 += zr[i].z * cv[i].z;
        a3 += zr[i].w * cv[i].w;
    }
    float dot = (a0 + a1) + (a2 + a3);
    return (z2 - 2.0f * dot) + c2;
}

__device__ __forceinline__ float z2_of(const float4* zr) {
    float z2 = 0.f;
    #pragma unroll
    for (int i = 0; i < 16; i++)
        z2 += zr[i].x * zr[i].x + zr[i].y * zr[i].y
            + zr[i].z * zr[i].z + zr[i].w * zr[i].w;
    return z2;
}

__device__ __forceinline__ uint32_t packh2(float x, float y) {
    __nv_half2_raw h2 = __halves2half2(__float2half_rn(x), __float2half_rn(y));
    return *(uint32_t*)&h2;
}

// A row: convert 64 f32 -> fp16, row-major words, return sum of squares
__device__ __forceinline__ float stage_row_fp16(char* dst, const float4* v) {
    float s = 0.f;
    #pragma unroll
    for (int i = 0; i < 16; i++) {
        float4 a = v[i];
        s += a.x * a.x + a.y * a.y + a.z * a.z + a.w * a.w;
        uint2 w;
        w.x = packh2(a.x, a.y);
        w.y = packh2(a.z, a.w);
        *(uint2*)(dst + i * 8) = w;
    }
    return s;
}

// B row: convert + store PERMUTED: thread (qr,qc) reads its 8 fragment words
// contiguously at byte offset qc*32.
__device__ __forceinline__ float stage_row_b_perm(char* dst, const float4* v) {
    float s = 0.f;
    uint32_t w[32];
    #pragma unroll
    for (int i = 0; i < 16; i++) {
        float4 a = v[i];
        s += a.x * a.x + a.y * a.y + a.z * a.z + a.w * a.w;
        w[2 * i]     = packh2(a.x, a.y);
        w[2 * i + 1] = packh2(a.z, a.w);
    }
    *(uint4*)(dst +   0) = make_uint4(w[0],  w[4],  w[8],  w[12]);
    *(uint4*)(dst +  16) = make_uint4(w[16], w[20], w[24], w[28]);
    *(uint4*)(dst +  32) = make_uint4(w[1],  w[5],  w[9],  w[13]);
    *(uint4*)(dst +  48) = make_uint4(w[17], w[21], w[25], w[29]);
    *(uint4*)(dst +  64) = make_uint4(w[2],  w[6],  w[10], w[14]);
    *(uint4*)(dst +  80) = make_uint4(w[18], w[22], w[26], w[30]);
    *(uint4*)(dst +  96) = make_uint4(w[3],  w[7],  w[11], w[15]);
    *(uint4*)(dst + 112) = make_uint4(w[19], w[23], w[27], w[31]);
    return s;
}

// ============================================================================
// Main kernel: persistent, 2 CTAs/SM, 8 warps, M-tile 256 (2 m16 strips/warp)
// ============================================================================
__global__ __launch_bounds__(TPB, 2)
void vq_mma(const float* __restrict__ z, const float* __restrict__ cb,
            int N, float* __restrict__ q_out, float* __restrict__ ids_out,
            float* __restrict__ loss_out)
{
    extern __shared__ char smem[];
    const int tid  = threadIdx.x;
    const int wid  = tid >> 5;
    const int lane = tid & 31;
    const int qr   = lane >> 5 ? 0 : (lane >> 2);   // 0..7
    const int qc   = lane & 3;    // 0..3

    float* c2n  = (float*)(smem + C2N_OFF);
    float* z2s  = (float*)(smem + Z2S_OFF);
    int*   kidS = (int*)(smem + KID_OFF);
    float* cnp  = (float*)(smem + CN_OFF);

    // ---- stage codebook once: permuted fp16 rows + -0.5*||c||^2 ----
    for (int n = tid; n < KCODES; n += TPB) {
        float4 cv[16];
        const float4* c4 = (const float4*)(cb + (size_t)n * D);
        #pragma unroll
        for (int i = 0; i < 16; i++) cv[i] = c4[i];
        float s = stage_row_b_perm(smem + B_OFF + n * 144, cv);
        c2n[n] = -0.5f * s;
    }
    __syncthreads();
    if (tid < 32) {
        float m = 0.f;
        for (int i = tid; i < KCODES; i += 32) m = fmaxf(m, -c2n[i]);
        #pragma unroll
        for (int off = 16; off; off >>= 1)
            m = fmaxf(m, __shfl_xor_sync(0xffffffffu, m, off));
        if (tid == 0) *cnp = sqrtf(2.0f * m);
    }
    __syncthreads();
    const float CNMAX = *cnp;

    const int ntiles = N / MTILE;
    double dsum = 0.0;

    for (int tile = blockIdx.x; tile < ntiles; tile += gridDim.x) {
        // ---- stage A tile: all 256 threads convert one row each ----
        {
            float4 zr[16];
            const float4* zp = (const float4*)(z + (size_t)(tile * MTILE + tid) * D);
            #pragma unroll
            for (int i = 0; i < 16; i++) zr[i] = zp[i];
            z2s[tid] = stage_row_fp16(smem + A_OFF + tid * 144, zr);
        }
        __syncthreads();

        // ---- A fragments (hoisted; 2 strips: rows wid*32+qr(+8), +16(+8)) ----
        uint32_t afr[2][4][4];
        #pragma unroll
        for (int st = 0; st < 2; st++) {
            const int r0b = (wid * 32 + st * 16 + qr) * 144;
            #pragma unroll
            for (int ks = 0; ks < 4; ks++) {
                const int kb = ks * 32 + qc * 4;
                afr[st][ks][0] = *(const uint32_t*)(smem + A_OFF + r0b + kb);
                afr[st][ks][1] = *(const uint32_t*)(smem + A_OFF + r0b + 8 * 144 + kb);
                afr[st][ks][2] = *(const uint32_t*)(smem + A_OFF + r0b + kb + 16);
                afr[st][ks][3] = *(const uint32_t*)(smem + A_OFF + r0b + 8 * 144 + kb + 16);
            }
        }

        // ---- MMA + per-thread packed-key top-3 for 4 row-slots ----
        uint32_t tkey[4][3];
        #pragma unroll
        for (int s = 0; s < 4; s++)
            tkey[s][0] = tkey[s][1] = tkey[s][2] = 0u;

        for (int grp = 0; grp < 32; grp++) {   // 32 groups of 16 codes
            float acc[2][2][4];                // [c][strip][frag]
            uint4 ra[2], rb[2];
            #pragma unroll
            for (int c = 0; c < 2; c++) {
                const int col0 = grp * 16 + c * 8 + qc * 2;
                const float2 nh = *(const float2*)&c2n[col0];
                #pragma unroll
                for (int st = 0; st < 2; st++) {
                    acc[c][st][0] = nh.x; acc[c][st][1] = nh.y;
                    acc[c][st][2] = nh.x; acc[c][st][3] = nh.y;
                }
                const char* bp = smem + B_OFF
                               + (grp * 16 + c * 8 + qr) * 144 + qc * 32;
                ra[c] = *(const uint4*)(bp);
                rb[c] = *(const uint4*)(bp + 16);
            }
            #pragma unroll
            for (int c = 0; c < 2; c++) {
                mma_fp16(acc[c][0], afr[0][0], ra[c].x, ra[c].y);
                mma_fp16(acc[c][1], afr[1][0], ra[c].x, ra[c].y);
            }
            #pragma unroll
            for (int c = 0; c < 2; c++) {
                mma_fp16(acc[c][0], afr[0][1], ra[c].z, ra[c].w);
                mma_fp16(acc[c][1], afr[1][1], ra[c].z, ra[c].w);
            }
            #pragma unroll
            for (int c = 0; c < 2; c++) {
                mma_fp16(acc[c][0], afr[0][2], rb[c].x, rb[c].y);
                mma_fp16(acc[c][1], afr[1][2], rb[c].x, rb[c].y);
            }
            #pragma unroll
            for (int c = 0; c < 2; c++) {
                mma_fp16(acc[c][0], afr[0][3], rb[c].z, rb[c].w);
                mma_fp16(acc[c][1], afr[1][3], rb[c].z, rb[c].w);
            }

            #pragma unroll
            for (int c = 0; c < 2; c++) {
                const int col0 = grp * 16 + c * 8 + qc * 2;
                const uint32_t i0 = 511 - col0;
                ins3k(mkkey(acc[c][0][0], i0),     tkey[0]);
                ins3k(mkkey(acc[c][0][1], i0 - 1), tkey[0]);
                ins3k(mkkey(acc[c][0][2], i0),     tkey[1]);
                ins3k(mkkey(acc[c][0][3], i0 - 1), tkey[1]);
                ins3k(mkkey(acc[c][1][0], i0),     tkey[2]);
                ins3k(mkkey(acc[c][1][1], i0 - 1), tkey[2]);
                ins3k(mkkey(acc[c][1][2], i0),     tkey[3]);
                ins3k(mkkey(acc[c][1][3], i0 - 1), tkey[3]);
            }
        }

        uint32_t loc3[4];
        #pragma unroll
        for (int s = 0; s < 4; s++) loc3[s] = tkey[s][2];

        // ---- quad merge (xor 1, 2) -> global top-3 per slot ----
        #pragma unroll
        for (int off = 1; off <= 2; off <<= 1) {
            #pragma unroll
            for (int s = 0; s < 4; s++) {
                uint32_t k0 = tkey[s][0], k1 = tkey[s][1], k2 = tkey[s][2];
                uint32_t o0 = __shfl_xor_sync(0xffffffffu, k0, off);
                uint32_t o1 = __shfl_xor_sync(0xffffffffu, k1, off);
                uint32_t o2 = __shfl_xor_sync(0xffffffffu, k2, off);
                ins3k(o0, tkey[s]);
                ins3k(o1, tkey[s]);
                ins3k(o2, tkey[s]);
            }
        }

        // ---- per-row rigorous threshold + coverage ballots (4 slots) ----
        // slot s row = wid*32 + (s>>1)*16 + (s&1)*8 + qr
        uint32_t cut[4];
        bool     uns[4];
        const unsigned qsh = lane & ~3;
        #pragma unroll
        for (int s = 0; s < 4; s++) {
            const int row = wid * 32 + (s >> 1) * 16 + (s & 1) * 8 + qr;
            const float thr = sqrtf(z2s[row]) * CNMAX * 0.001953125f + 1.2e-3f;
            const float b1b = __uint_as_float(tkey[s][0] & KEYMASK);
            cut[s] = __float_as_uint(b1b - thr) & KEYMASK;
            unsigned bal = __ballot_sync(0xffffffffu, loc3[s] >= cut[s]);
            uns[s] = ((bal >> qsh) & 0xFu) != 0;
        }

        // ---- finalize: lane qc owns slot qc ----
        const int  myrow = wid * 32 + (qc >> 1) * 16 + (qc & 1) * 8 + qr;
        const bool my_unsafe = uns[qc];
        int kid = 0;

        if (!my_unsafe) {
            const uint32_t K0 = tkey[qc][0], K1 = tkey[qc][1], K2 = tkey[qc][2];
            const uint32_t mycut = cut[qc];
            int ck[3]; int nc = 1;
            ck[0] = 511 - (int)(K0 & 0x1FFu);
            if (K1 >= mycut) ck[nc++] = 511 - (int)(K1 & 0x1FFu);
            if (K2 >= mycut) ck[nc++] = 511 - (int)(K2 & 0x1FFu);
            if (nc == 1) {
                kid = ck[0];                            // margin proves winner
            } else {
                if (ck[0] > ck[1]) { int t = ck[0]; ck[0] = ck[1]; ck[1] = t; }
                if (nc == 3) {
                    if (ck[1] > ck[2]) { int t = ck[1]; ck[1] = ck[2]; ck[2] = t; }
                    if (ck[0] > ck[1]) { int t = ck[0]; ck[0] = ck[1]; ck[1] = t; }
                }
                const int grow = tile * MTILE + myrow;
                float4 zr[16];
                const float4* zp = (const float4*)(z + (size_t)grow * D);
                #pragma unroll
                for (int i = 0; i < 16; i++) zr[i] = zp[i];
                const float z2 = z2_of(zr);
                float best = 3.402823466e38f; kid = ck[0];
                for (int i = 0; i < nc; i++) {          // ascending k, strict <
                    float d = exact_d2(zr, z2, cb + (size_t)ck[i] * D);
                    if (d < best) { best = d; kid = ck[i]; }
                }
            }
        }

        // ---- warp-cooperative exact scan for unsafe rows (rare) ----
        unsigned need = __ballot_sync(0xffffffffu, my_unsafe);
        while (need) {
            const int src = __ffs(need) - 1;
            need &= need - 1;
            const int rl = __shfl_sync(0xffffffffu, myrow, src);
            const int grow = tile * MTILE + rl;
            float4 zr[16];
            const float4* zp = (const float4*)(z + (size_t)grow * D);
            #pragma unroll
            for (int i = 0; i < 16; i++) zr[i] = zp[i];
            const float z2 = z2_of(zr);
            float best = 3.402823466e38f; int bk = KCODES;
            for (int k = lane; k < KCODES; k += 32) {   // lane-ascending, strict <
                float d = exact_d2(zr, z2, cb + (size_t)k * D);
                if (d < best) { best = d; bk = k; }
            }
            #pragma unroll
            for (int off = 16; off; off >>= 1) {
                float ob = __shfl_xor_sync(0xffffffffu, best, off);
                int   obk = __shfl_xor_sync(0xffffffffu, bk, off);
                if (ob < best || (ob == best && obk < bk)) { best = ob; bk = obk; }
            }
            if (lane == src) kid = bk;
        }

        kidS[myrow] = kid;
        __syncthreads();

        // ---- epilogue: all 256 threads, row tid ----
        {
            const int grow = tile * MTILE + tid;
            const int k = kidS[tid];
            float4 zr[16];
            const float4* zp = (const float4*)(z + (size_t)grow * D);
            #pragma unroll
            for (int i = 0; i < 16; i++) zr[i] = zp[i];
            const float4* q4 = (const float4*)(cb + (size_t)k * D);
            float4* qo = (float4*)(q_out + (size_t)grow * D);
            float lsum = 0.f;
            #pragma unroll
            for (int i = 0; i < 16; i++) {
                float4 cv = q4[i];
                float4 zv = zr[i];
                float dx = zv.x - cv.x, dy = zv.y - cv.y;
                float dz = zv.z - cv.z, dw = zv.w - cv.w;
                lsum += dx * dx + dy * dy + dz * dz + dw * dw;
                float4 o;
                o.x = zv.x + (cv.x - zv.x);   // fl(z + fl(q - z)), reference STE
                o.y = zv.y + (cv.y - zv.y);
                o.z = zv.z + (cv.z - zv.z);
                o.w = zv.w + (cv.w - zv.w);
                qo[i] = o;
            }
            if (ids_out) ids_out[grow] = (float)k;
            dsum += (double)lsum;
        }
        __syncthreads();   // kidS/A protected before next iteration's writes
    }

    // ---- deterministic per-CTA loss reduction ----
    double* red = (double*)(smem + B_OFF);   // codebook region reusable now
    red[tid] = dsum;
    __syncthreads();
    if (tid == 0) {
        double s = 0.0;
        for (int i = 0; i < TPB; i++) s += red[i];
        g_partial[blockIdx.x] = s;
    }

    // ---- fused finalize: last CTA computes the loss (deterministic order) ----
    if (loss_out) {
        __shared__ unsigned s_last;
        if (tid == 0) {
            __threadfence();
            unsigned p = atomicAdd(&g_count, 1u);
            s_last = (p == gridDim.x - 1) ? 1u : 0u;
        }
        __syncthreads();
        if (s_last) {
            __threadfence();
            double s = 0.0;
            for (int i = tid; i < (int)gridDim.x; i += TPB) s += g_partial[i];
            double* sp = (double*)(smem + B_OFF);
            __syncthreads();
            sp[tid] = s;
            __syncthreads();
            for (int off = TPB / 2; off; off >>= 1) {
                if (tid < off) sp[tid] += sp[tid + off];
                __syncthreads();
            }
            if (tid == 0) {
                double mean = sp[0] / ((double)N * (double)D);
                loss_out[0] = (float)(mean + 0.25 * mean);
                g_count = 0;                 // reset for graph replay
            }
        }
    }
}

// ============================================================================
// Generic fallback (round-2 kernel) for unexpected shapes
// ============================================================================
#define FTPB 256
#define ROW_PAD 68
__global__ __launch_bounds__(FTPB) void vq_ref(
    const float* __restrict__ z, const float* __restrict__ cb,
    int N, int K, float* __restrict__ q_out, float* __restrict__ ids_out)
{
    extern __shared__ float fsm[];
    float* cbs = fsm;
    float* c2  = fsm + (size_t)K * ROW_PAD;
    const int tid = threadIdx.x;
    const float4* cb4 = (const float4*)cb;
    const int nvec = K * (D / 4);
    for (int idx = tid; idx < nvec; idx += FTPB) {
        int k = idx >> 4, c = idx & 15;
        *(float4*)&cbs[k * ROW_PAD + c * 4] = cb4[idx];
    }
    __syncthreads();
    for (int k = tid; k < K; k += FTPB) {
        const float* r = &cbs[k * ROW_PAD];
        float s = 0.f;
        #pragma unroll
        for (int i = 0; i < D; i++) s += r[i] * r[i];
        c2[k] = s;
    }
    __syncthreads();
    const int row = blockIdx.x * FTPB + tid;
    float lsum = 0.f;
    if (row < N) {
        float4 zr[16];
        const float4* zp = (const float4*)(z + (size_t)row * D);
        #pragma unroll
        for (int i = 0; i < 16; i++) zr[i] = zp[i];
        float z2 = 0.f;
        #pragma unroll
        for (int i = 0; i < 16; i++)
            z2 += zr[i].x * zr[i].x + zr[i].y * zr[i].y
                + zr[i].z * zr[i].z + zr[i].w * zr[i].w;
        float best = 3.402823466e38f; int bid = 0;
        for (int k = 0; k < K; k++) {
            const float4* crow = (const float4*)&cbs[k * ROW_PAD];
            float a0 = 0.f, a1 = 0.f, a2 = 0.f, a3 = 0.f;
            #pragma unroll
            for (int i = 0; i < 16; i++) {
                float4 cv = crow[i];
                a0 += zr[i].x * cv.x; a1 += zr[i].y * cv.y;
                a2 += zr[i].z * cv.z; a3 += zr[i].w * cv.w;
            }
            float dot = (a0 + a1) + (a2 + a3);
            float d = (z2 - 2.0f * dot) + c2[k];
            if (d < best) { best = d; bid = k; }
        }
        const float4* crow = (const float4*)&cbs[bid * ROW_PAD];
        float4* qo = (float4*)(q_out + (size_t)row * D);
        #pragma unroll
        for (int i = 0; i < 16; i++) {
            float4 cv = crow[i];
            float4 zv = zr[i];
            float dx = zv.x - cv.x, dy = zv.y - cv.y;
            float dz = zv.z - cv.z, dw = zv.w - cv.w;
            lsum += dx * dx + dy * dy + dz * dz + dw * dw;
            float4 o;
            o.x = zv.x + (cv.x - zv.x); o.y = zv.y + (cv.y - zv.y);
            o.z = zv.z + (cv.z - zv.z); o.w = zv.w + (cv.w - zv.w);
            qo[i] = o;
        }
        if (ids_out) ids_out[row] = (float)bid;
    }
    #pragma unroll
    for (int off = 16; off; off >>= 1)
        lsum += __shfl_down_sync(0xffffffffu, lsum, off);
    __shared__ double wp[FTPB / 32];
    if ((tid & 31) == 0) wp[tid >> 5] = (double)lsum;
    __syncthreads();
    if (tid == 0) {
        double s = 0.0;
        #pragma unroll
        for (int w = 0; w < FTPB / 32; w++) s += wp[w];
        g_partial[blockIdx.x] = s;
    }
}

__global__ void vq_finalize(int nblocks, double inv_total, float* loss_out)
{
    __shared__ double sp[256];
    const int tid = threadIdx.x;
    double s = 0.0;
    for (int i = tid; i < nblocks; i += 256) s += g_partial[i];
    sp[tid] = s;
    __syncthreads();
    for (int off = 128; off; off >>= 1) {
        if (tid < off) sp[tid] += sp[tid + off];
        __syncthreads();
    }
    if (tid == 0) {
        double mean = sp[0] * inv_total;
        loss_out[0] = (float)(mean + 0.25 * mean);
    }
}

extern "C" void kernel_launch(void* const* d_in, const int* in_sizes, int n_in,
                              void* d_out, int out_size)
{
    const float* z  = (const float*)d_in[0];
    const float* cb = (const float*)d_in[1];
    const int N = in_sizes[0] / D;
    const int K = in_sizes[1] / D;

    float* out = (float*)d_out;
    float* q_out    = out;
    float* loss_ptr = nullptr;
    float* ids_ptr  = nullptr;
    const long base = (long)N * D;
    if ((long)out_size >= base + 1 + N) { loss_ptr = out + base; ids_ptr = out + base + 1; }
    else if ((long)out_size == base + N) { ids_ptr = out + base; }
    else if ((long)out_size == base + 1) { loss_ptr = out + base; }

    if (K == KCODES && (N % MTILE) == 0 && N > 0) {
        const int ntiles = N / MTILE;
        const int nblocks = ntiles < GRID_MAX ? ntiles : GRID_MAX;
        cudaFuncSetAttribute(vq_mma, cudaFuncAttributeMaxDynamicSharedMemorySize, SMEM_TOTAL);
        vq_mma<<<nblocks, TPB, SMEM_TOTAL>>>(z, cb, N, q_out, ids_ptr, loss_ptr);
    } else {
        const size_t smem_bytes = ((size_t)K * ROW_PAD + K) * sizeof(float);
        cudaFuncSetAttribute(vq_ref, cudaFuncAttributeMaxDynamicSharedMemorySize, (int)smem_bytes);
        const int nblocks = (N + FTPB - 1) / FTPB;
        vq_ref<<<nblocks, FTPB, smem_bytes>>>(z, cb, N, K, q_out, ids_ptr);
        if (loss_ptr) {
            double inv_total = 1.0 / ((double)N * (double)D);
            vq_finalize<<<1, 256>>>(nblocks, inv_total, loss_ptr);
        }
    }
}